// round 4
// baseline (speedup 1.0000x reference)
#include <cuda_runtime.h>
#include <cstdint>
#include <math_constants.h>

#define BATCH 131072
#define NRB   1024

#if defined(__CUDA_ARCH_FEAT_SM103_ALL) || defined(__CUDA_ARCH_FEAT_SM100_ALL) || defined(__CUDA_ARCH_FEAT_SM101_ALL)
#define HAS_TCGEN05 1
#else
#define HAS_TCGEN05 0
#endif

// ---------------- scratch ----------------------------------------------------
__device__ float g_a1[BATCH * 128];
__device__ float g_a2[BATCH * 256];
__device__ float g_a3[BATCH * 128];
__device__ float g_psum[NRB * 256];
__device__ float g_psq [NRB * 256];
__device__ float g_scale[256];
__device__ float g_shift[256];

// ---------------- ptx helpers -------------------------------------------------
__device__ __forceinline__ uint32_t smem_u32(const void* p) {
    uint32_t a;
    asm("{ .reg .u64 t; cvta.to.shared.u64 t, %1; cvt.u32.u64 %0, t; }" : "=r"(a) : "l"(p));
    return a;
}

#if HAS_TCGEN05
__device__ __forceinline__ uint32_t elect1() {
    uint32_t p;
    asm volatile("{\n\t.reg .pred p;\n\telect.sync _|p, 0xFFFFFFFF;\n\tselp.b32 %0, 1, 0, p;\n\t}" : "=r"(p));
    return p;
}
#define TCGEN05_ALLOC(smem_addr, nCols) \
    asm volatile("tcgen05.alloc.cta_group::1.sync.aligned.shared::cta.b32 [%0], %1;" \
                 :: "r"((uint32_t)(smem_addr)), "r"((uint32_t)(nCols)) : "memory")
#define TCGEN05_DEALLOC(tmem_addr, nCols) \
    asm volatile("tcgen05.dealloc.cta_group::1.sync.aligned.b32 %0, %1;" \
                 :: "r"(tmem_addr), "r"((uint32_t)(nCols)))
#define TCGEN05_RELINQ() \
    asm volatile("tcgen05.relinquish_alloc_permit.cta_group::1.sync.aligned;")
#define TCGEN05_COMMIT(mbar_smem_addr) \
    asm volatile("tcgen05.commit.cta_group::1.mbarrier::arrive::one.shared::cluster.b64 [%0];" \
                 :: "r"((uint32_t)(mbar_smem_addr)) : "memory")
#define TCGEN05_FENCE_AFTER() \
    asm volatile("tcgen05.fence::after_thread_sync;" ::: "memory")
#define TCGEN05_WAIT_LD() \
    asm volatile("tcgen05.wait::ld.sync.aligned;" ::: "memory")
#define MBARRIER_INIT(mbar_smem_addr, count) \
    asm volatile("mbarrier.init.shared.b64 [%0], %1;" \
                 :: "r"((uint32_t)(mbar_smem_addr)), "r"((uint32_t)(count)) : "memory")
#define MBARRIER_WAIT_PARITY(mbar_smem_addr, phase_parity) do { \
    uint32_t _mbar = (uint32_t)(mbar_smem_addr); \
    uint32_t _parity = (uint32_t)(phase_parity); \
    uint32_t _done; \
    asm volatile("{\n\t.reg .pred p;\n\t" \
        "mbarrier.try_wait.parity.acquire.cta.shared::cta.b64 p, [%1], %2;\n\t" \
        "selp.b32 %0, 1, 0, p;\n\t}" \
        : "=r"(_done) : "r"(_mbar), "r"(_parity) : "memory"); \
    if (!_done) { \
        asm volatile("{\n\t.reg .pred P1;\n\t" \
            "WAIT_LOOP_%=:\n\t" \
            "mbarrier.try_wait.parity.acquire.cta.shared::cta.b64 P1, [%0], %1, 0x989680;\n\t" \
            "@P1 bra.uni WAIT_DONE_%=;\n\t" \
            "bra.uni WAIT_LOOP_%=;\n\t" \
            "WAIT_DONE_%=:\n\t}" \
            :: "r"(_mbar), "r"(_parity) : "memory"); \
    } \
} while (0)
#define TCGEN05_LD_32X32B_X32(r, tmem_addr) \
    asm volatile("tcgen05.ld.sync.aligned.32x32b.x32.b32 " \
        "{%0, %1, %2, %3, %4, %5, %6, %7, " \
        " %8, %9, %10, %11, %12, %13, %14, %15, " \
        " %16, %17, %18, %19, %20, %21, %22, %23, " \
        " %24, %25, %26, %27, %28, %29, %30, %31}, [%32];" \
        : "=r"((r)[0]),  "=r"((r)[1]),  "=r"((r)[2]),  "=r"((r)[3]), \
          "=r"((r)[4]),  "=r"((r)[5]),  "=r"((r)[6]),  "=r"((r)[7]), \
          "=r"((r)[8]),  "=r"((r)[9]),  "=r"((r)[10]), "=r"((r)[11]), \
          "=r"((r)[12]), "=r"((r)[13]), "=r"((r)[14]), "=r"((r)[15]), \
          "=r"((r)[16]), "=r"((r)[17]), "=r"((r)[18]), "=r"((r)[19]), \
          "=r"((r)[20]), "=r"((r)[21]), "=r"((r)[22]), "=r"((r)[23]), \
          "=r"((r)[24]), "=r"((r)[25]), "=r"((r)[26]), "=r"((r)[27]), \
          "=r"((r)[28]), "=r"((r)[29]), "=r"((r)[30]), "=r"((r)[31]) \
        : "r"(tmem_addr))

__device__ __forceinline__ uint64_t sdesc(uint32_t addr) {
    // SW128, version=1 (Blackwell), SBO=64, LBO=1, K-major
    return ((uint64_t)2 << 61) | ((uint64_t)1 << 46) | ((uint64_t)64 << 32) |
           ((uint64_t)1 << 16) | ((uint64_t)(addr >> 4) & 0x3FFF);
}
__device__ __forceinline__ void mma_tf32_ss(uint32_t d, uint64_t ad, uint64_t bd,
                                            uint32_t idesc, uint32_t en) {
    asm volatile("{\n\t.reg .pred p;\n\tsetp.ne.u32 p, %4, 0;\n\t"
        "tcgen05.mma.cta_group::1.kind::tf32 [%0], %1, %2, %3, {%5, %5, %5, %5}, p;\n\t}"
        :: "r"(d), "l"(ad), "l"(bd), "r"(idesc), "r"(en), "r"(0u) : "memory");
}
#endif // HAS_TCGEN05

#define SW128(o) ((o) ^ (((o) >> 3) & 0x70))

// ---------------------------------------------------------------------------
// GEMM: C[B,N] = act(A[B,K]) @ W[K,N] + bias, act = folded BN+lrelu of prev
// layer when ACT. Deterministic per-rowblock column stats into g_psum/g_psq.
// tcgen05 path: 3xTF32 split, D in TMEM, TWO-STAGE double-buffered pipeline
// (fill chunk ch+1 overlaps async MMA of chunk ch). 1 CTA/SM.
// ---------------------------------------------------------------------------
// smem layout (after 1KB alignment pad):
//   stage s (s=0,1) at s*65536: Ah +0, Al +16K, Bh +32K, Bl +48K (each 16KB)
//   131072: sSc (1KB), 132096: sSh (1KB), 133120: sB (512B), 133632: red (2KB)
//   epilogue 'stage' staging reuses stage0 (34.3KB needed)
#define GEMM_SMEM (140 * 1024)

template<int KDIM, bool ACT>
__global__ __launch_bounds__(256, 1)
void gemm_tc(const float* __restrict__ A, const float* __restrict__ W,
             const float* __restrict__ bias, float* __restrict__ C, int N)
{
#if HAS_TCGEN05
    constexpr int NCH = (KDIM + 31) / 32;
    extern __shared__ char dsm[];
    const uint32_t sb0 = smem_u32(dsm);
    const uint32_t pad = ((sb0 + 1023) & ~1023u) - sb0;
    char* bp = dsm + pad;
    const uint32_t sbu = sb0 + pad;

    float* stage = (float*)bp;                // epilogue staging (reuse stage0)
    float* sSc   = (float*)(bp + 131072);
    float* sSh   = (float*)(bp + 132096);
    float* sB    = (float*)(bp + 133120);
    float* redS  = (float*)(bp + 133632);     // 4 x 64
    float* redQ  = (float*)(bp + 134656);     // 4 x 64

    __shared__ uint64_t s_mbar[2];
    __shared__ uint32_t s_tptr;
    const uint32_t mbA[2] = { smem_u32(&s_mbar[0]), smem_u32(&s_mbar[1]) };

    const int tid  = threadIdx.x;
    const int wid  = tid >> 5;
    const int lane = tid & 31;
    const int row0 = blockIdx.x * 128;
    const int col0 = blockIdx.y * 128;

    if (ACT) {
        for (int i = tid; i < KDIM; i += 256) { sSc[i] = g_scale[i]; sSh[i] = g_shift[i]; }
    }
    for (int i = tid; i < 128; i += 256) sB[i] = bias[col0 + i];
    if (tid == 0) { MBARRIER_INIT(mbA[0], 1); MBARRIER_INIT(mbA[1], 1); }
    if (wid == 0) TCGEN05_ALLOC(smem_u32(&s_tptr), 128);
    __syncthreads();
    const uint32_t tmem = s_tptr;

    const uint32_t IDESC = (1u << 4) | (2u << 7) | (2u << 10) | (16u << 17) | (8u << 24);

    for (int ch = 0; ch < NCH; ch++) {
        const int st  = ch & 1;
        const int use = ch >> 1;
        const uint32_t mb = mbA[st];
        if (use >= 1) { MBARRIER_WAIT_PARITY(mb, (use - 1) & 1); }

        char* pAh = bp + st * 65536;
        char* pAl = pAh + 16384;
        char* pBh = pAh + 32768;
        char* pBl = pAh + 49152;
        const int k0 = ch * 32;

#pragma unroll
        for (int i = 0; i < 16; i++) {
            int idx = tid + i * 256;
            int m = idx >> 5, kk = idx & 31, k = k0 + kk;
            float v = 0.f;
            if ((KDIM % 32 == 0) || k < KDIM) {
                v = A[(size_t)(row0 + m) * KDIM + k];
                if (ACT) {
                    v = fmaf(v, sSc[k], sSh[k]);
                    v = v > 0.f ? v : 0.2f * v;
                }
            }
            uint32_t hb; asm("cvt.rna.tf32.f32 %0, %1;" : "=r"(hb) : "f"(v));
            float lo = v - __uint_as_float(hb);
            uint32_t off = SW128((uint32_t)(m * 128 + kk * 4));
            *(uint32_t*)(pAh + off) = hb;
            *(float*)   (pAl + off) = lo;
        }
#pragma unroll
        for (int i = 0; i < 16; i++) {
            int idx = tid + i * 256;
            int kk = idx >> 7, n = idx & 127, k = k0 + kk;
            float v = ((KDIM % 32 == 0) || k < KDIM) ? W[(size_t)k * N + col0 + n] : 0.f;
            uint32_t hb; asm("cvt.rna.tf32.f32 %0, %1;" : "=r"(hb) : "f"(v));
            float lo = v - __uint_as_float(hb);
            uint32_t off = SW128((uint32_t)(n * 128 + kk * 4));
            *(uint32_t*)(pBh + off) = hb;
            *(float*)   (pBl + off) = lo;
        }
        asm volatile("fence.proxy.async.shared::cta;" ::: "memory");
        __syncthreads();

        if (wid == 0 && elect1()) {
            const uint32_t sAh = sbu + st * 65536;
            uint64_t adh = sdesc(sAh),         adl = sdesc(sAh + 16384);
            uint64_t bdh = sdesc(sAh + 32768), bdl = sdesc(sAh + 49152);
#pragma unroll
            for (int ks = 0; ks < 4; ks++) {
                uint32_t en0 = (ch == 0 && ks == 0) ? 0u : 1u;
                mma_tf32_ss(tmem, adh + ks * 2, bdh + ks * 2, IDESC, en0);
                mma_tf32_ss(tmem, adh + ks * 2, bdl + ks * 2, IDESC, 1u);
                mma_tf32_ss(tmem, adl + ks * 2, bdh + ks * 2, IDESC, 1u);
            }
            TCGEN05_COMMIT(mb);  // commit tracks ALL prior MMAs from this thread
        }
        // no wait here: next iteration fills the other stage while MMAs run
    }
    // final wait: last commit covers every MMA issued
    MBARRIER_WAIT_PARITY(mbA[(NCH - 1) & 1], ((NCH - 1) >> 1) & 1);
    TCGEN05_FENCE_AFTER();
    __syncthreads();   // everyone past the wait before stage0 smem is reused

    // ---- epilogue: two 64-col halves through smem staging ----
    const int rw = wid & 3, cg = wid >> 2;
#pragma unroll 1
    for (int h = 0; h < 2; h++) {
        uint32_t regs[32];
        TCGEN05_LD_32X32B_X32(regs, tmem + h * 64 + cg * 32);
        TCGEN05_WAIT_LD();
        const int row = rw * 32 + lane;
#pragma unroll
        for (int j = 0; j < 32; j++) {
            float v = __uint_as_float(regs[j]) + sB[h * 64 + cg * 32 + j];
            stage[row * 67 + cg * 32 + j] = v;
        }
        __syncthreads();
        {   // coalesced store
            const int col = tid & 63, rg4 = tid >> 6;
#pragma unroll 4
            for (int it = 0; it < 32; it++) {
                int r = it * 4 + rg4;
                C[(size_t)(row0 + r) * N + col0 + h * 64 + col] = stage[r * 67 + col];
            }
        }
        {   // column stats: 4 row-groups x 64 cols, all 8 warps busy
            const int col = tid & 63, rg = tid >> 6;
            float s = 0.f, q = 0.f;
#pragma unroll 8
            for (int r = rg * 32; r < rg * 32 + 32; r++) {
                float v = stage[r * 67 + col];
                s += v; q = fmaf(v, v, q);
            }
            redS[rg * 64 + col] = s;
            redQ[rg * 64 + col] = q;
        }
        __syncthreads();
        if (tid < 64) {
            float s = redS[tid] + redS[64 + tid] + redS[128 + tid] + redS[192 + tid];
            float q = redQ[tid] + redQ[64 + tid] + redQ[128 + tid] + redQ[192 + tid];
            g_psum[(size_t)blockIdx.x * N + col0 + h * 64 + tid] = s;
            g_psq [(size_t)blockIdx.x * N + col0 + h * 64 + tid] = q;
        }
        __syncthreads();
    }

    if (wid == 0) { TCGEN05_RELINQ(); TCGEN05_DEALLOC(tmem, 128); }

#else
    // ======================= FFMA fallback (compiles on plain sm_103) =====
    extern __shared__ char dsm[];
    float (*As)[128] = (float(*)[128])dsm;
    float (*Ws)[128] = (float(*)[128])(dsm + 8192);
    float* sSc = (float*)(dsm + 16384);
    float* sSh = (float*)(dsm + 17408);

    const int tid  = threadIdx.x;
    const int row0 = blockIdx.x * 128;
    const int col0 = blockIdx.y * 128;

    if (ACT) {
        for (int i = tid; i < KDIM; i += 256) { sSc[i] = g_scale[i]; sSh[i] = g_shift[i]; }
        __syncthreads();
    }
    const int ty = tid >> 4;
    const int tx = tid & 15;

    float acc[8][8];
#pragma unroll
    for (int i = 0; i < 8; i++)
#pragma unroll
        for (int j = 0; j < 8; j++) acc[i][j] = 0.f;

    for (int k0 = 0; k0 < KDIM; k0 += 16) {
#pragma unroll
        for (int l = 0; l < 8; l++) {
            int idx = tid + l * 256;
            int m = idx >> 4, kk = idx & 15;
            int k = k0 + kk;
            float v = 0.f;
            if ((KDIM % 16 == 0) || k < KDIM) {
                v = A[(size_t)(row0 + m) * KDIM + k];
                if (ACT) {
                    v = fmaf(v, sSc[k], sSh[k]);
                    v = v > 0.f ? v : 0.2f * v;
                }
            }
            As[kk][m] = v;
        }
#pragma unroll
        for (int l = 0; l < 8; l++) {
            int idx = tid + l * 256;
            int kk = idx >> 7, n = idx & 127;
            int k = k0 + kk;
            Ws[kk][n] = ((KDIM % 16 == 0) || k < KDIM) ? W[(size_t)k * N + col0 + n] : 0.f;
        }
        __syncthreads();
#pragma unroll
        for (int kk = 0; kk < 16; kk++) {
            float4 a0 = *(const float4*)&As[kk][ty * 8];
            float4 a1 = *(const float4*)&As[kk][ty * 8 + 4];
            float4 w0 = *(const float4*)&Ws[kk][tx * 8];
            float4 w1 = *(const float4*)&Ws[kk][tx * 8 + 4];
            float a[8] = {a0.x, a0.y, a0.z, a0.w, a1.x, a1.y, a1.z, a1.w};
            float w[8] = {w0.x, w0.y, w0.z, w0.w, w1.x, w1.y, w1.z, w1.w};
#pragma unroll
            for (int i = 0; i < 8; i++)
#pragma unroll
                for (int j = 0; j < 8; j++)
                    acc[i][j] = fmaf(a[i], w[j], acc[i][j]);
        }
        __syncthreads();
    }

    float bj[8];
#pragma unroll
    for (int j = 0; j < 8; j++) bj[j] = bias[col0 + tx * 8 + j];
    float cs[8], cq[8];
#pragma unroll
    for (int j = 0; j < 8; j++) { cs[j] = 0.f; cq[j] = 0.f; }
#pragma unroll
    for (int i = 0; i < 8; i++) {
        float v[8];
#pragma unroll
        for (int j = 0; j < 8; j++) {
            v[j] = acc[i][j] + bj[j];
            cs[j] += v[j];
            cq[j] = fmaf(v[j], v[j], cq[j]);
        }
        float* cptr = &C[(size_t)(row0 + ty * 8 + i) * N + col0 + tx * 8];
        *(float4*)cptr       = make_float4(v[0], v[1], v[2], v[3]);
        *(float4*)(cptr + 4) = make_float4(v[4], v[5], v[6], v[7]);
    }
    float* red = &As[0][0];
    __syncthreads();
#pragma unroll
    for (int j = 0; j < 8; j++) red[ty * 128 + tx * 8 + j] = cs[j];
    __syncthreads();
    if (tid < 128) {
        float s = 0.f;
#pragma unroll
        for (int r = 0; r < 16; r++) s += red[r * 128 + tid];
        g_psum[(size_t)blockIdx.x * N + col0 + tid] = s;
    }
    __syncthreads();
#pragma unroll
    for (int j = 0; j < 8; j++) red[ty * 128 + tx * 8 + j] = cq[j];
    __syncthreads();
    if (tid < 128) {
        float s = 0.f;
#pragma unroll
        for (int r = 0; r < 16; r++) s += red[r * 128 + tid];
        g_psq[(size_t)blockIdx.x * N + col0 + tid] = s;
    }
#endif
}

// ---------------------------------------------------------------------------
__global__ void stats_kernel(const float* __restrict__ gamma,
                             const float* __restrict__ beta, int N)
{
    __shared__ float ss[128], qq[128];
    const int c = blockIdx.x;
    const int t = threadIdx.x;
    float s = 0.f, q = 0.f;
    for (int r = t; r < NRB; r += 128) {
        s += g_psum[(size_t)r * N + c];
        q += g_psq [(size_t)r * N + c];
    }
    ss[t] = s; qq[t] = q;
    __syncthreads();
    for (int off = 64; off > 0; off >>= 1) {
        if (t < off) { ss[t] += ss[t + off]; qq[t] += qq[t + off]; }
        __syncthreads();
    }
    if (t == 0) {
        float mean = ss[0] * (1.0f / (float)BATCH);
        float var  = qq[0] * (1.0f / (float)BATCH) - mean * mean;
        float inv  = rsqrtf(var + 1e-5f);
        float scl  = gamma[c] * inv;
        g_scale[c] = scl;
        g_shift[c] = beta[c] - mean * scl;
    }
}

// ---------------------------------------------------------------------------
__global__ __launch_bounds__(128)
void final_kernel(const float* __restrict__ W4, const float* __restrict__ b4,
                  const float* __restrict__ U, float* __restrict__ out)
{
    __shared__ float w4s[128 * 25];
    __shared__ float b4s[25];
    __shared__ float sc[128], sh[128];
    __shared__ float us[128 * 25];

    const int tid  = threadIdx.x;
    const int row0 = blockIdx.x * 128;
    const int row  = row0 + tid;

    for (int i = tid; i < 128 * 25; i += 128) w4s[i] = W4[i];
    if (tid < 25) b4s[tid] = b4[tid];
    sc[tid] = g_scale[tid];
    sh[tid] = g_shift[tid];
    __syncthreads();

    float lgt[25];
#pragma unroll
    for (int j = 0; j < 25; j++) lgt[j] = b4s[j];

    const float* arow = g_a3 + (size_t)row * 128;
    for (int k = 0; k < 128; k += 4) {
        float4 a4 = *(const float4*)(arow + k);
        float hv[4] = {a4.x, a4.y, a4.z, a4.w};
#pragma unroll
        for (int t = 0; t < 4; t++) {
            float h = fmaf(hv[t], sc[k + t], sh[k + t]);
            h = h > 0.f ? h : 0.2f * h;
#pragma unroll
            for (int j = 0; j < 25; j++)
                lgt[j] = fmaf(h, w4s[(k + t) * 25 + j], lgt[j]);
        }
    }

    unsigned mask = 0x1FFFFFFu;
#pragma unroll 1
    for (int s = 0; s < 15; s++) {
        __syncthreads();
        const float* ub = U + ((size_t)s * BATCH + row0) * 25;
        for (int i = tid; i < 128 * 25; i += 128) us[i] = ub[i];
        __syncthreads();

        float best = -CUDART_INF_F;
        int bi = __ffs(mask) - 1;
#pragma unroll
        for (int j = 0; j < 25; j++) {
            if (mask & (1u << j)) {
                float uu = us[tid * 25 + j];
                float nz = -__logf(-__logf(uu));
                float v  = lgt[j] + nz;
                if (v > best) { best = v; bi = j; }
            }
        }
        mask &= ~(1u << bi);
        out[(size_t)row * 15 + s] = (float)bi / 24.0f;
    }
}

// ---------------------------------------------------------------------------
extern "C" void kernel_launch(void* const* d_in, const int* in_sizes, int n_in,
                              void* d_out, int out_size)
{
    const float* z   = (const float*)d_in[0];
    const float* u   = (const float*)d_in[1];
    const float* W1  = (const float*)d_in[2];
    const float* b1  = (const float*)d_in[3];
    const float* g1  = (const float*)d_in[4];
    const float* be1 = (const float*)d_in[5];
    const float* W2  = (const float*)d_in[6];
    const float* b2  = (const float*)d_in[7];
    const float* g2  = (const float*)d_in[8];
    const float* be2 = (const float*)d_in[9];
    const float* W3  = (const float*)d_in[10];
    const float* b3  = (const float*)d_in[11];
    const float* g3  = (const float*)d_in[12];
    const float* be3 = (const float*)d_in[13];
    const float* W4  = (const float*)d_in[14];
    const float* b4  = (const float*)d_in[15];
    float* out = (float*)d_out;

    float *a1, *a2, *a3;
    cudaGetSymbolAddress((void**)&a1, g_a1);
    cudaGetSymbolAddress((void**)&a2, g_a2);
    cudaGetSymbolAddress((void**)&a3, g_a3);

    cudaFuncSetAttribute(gemm_tc<50,  false>, cudaFuncAttributeMaxDynamicSharedMemorySize, GEMM_SMEM);
    cudaFuncSetAttribute(gemm_tc<128, true >, cudaFuncAttributeMaxDynamicSharedMemorySize, GEMM_SMEM);
    cudaFuncSetAttribute(gemm_tc<256, true >, cudaFuncAttributeMaxDynamicSharedMemorySize, GEMM_SMEM);

    gemm_tc<50,  false><<<dim3(NRB, 1), 256, GEMM_SMEM>>>(z,  W1, b1, a1, 128);
    stats_kernel<<<128, 128>>>(g1, be1, 128);
    gemm_tc<128, true ><<<dim3(NRB, 2), 256, GEMM_SMEM>>>(a1, W2, b2, a2, 256);
    stats_kernel<<<256, 128>>>(g2, be2, 256);
    gemm_tc<256, true ><<<dim3(NRB, 1), 256, GEMM_SMEM>>>(a2, W3, b3, a3, 128);
    stats_kernel<<<128, 128>>>(g3, be3, 128);
    final_kernel<<<NRB, 128>>>(W4, b4, u, out);
}

// round 5
// speedup vs baseline: 1.1335x; 1.1335x over previous
#include <cuda_runtime.h>
#include <cstdint>
#include <math_constants.h>

#define BATCH 131072
#define NRB   1024

#if defined(__CUDA_ARCH_FEAT_SM103_ALL) || defined(__CUDA_ARCH_FEAT_SM100_ALL) || defined(__CUDA_ARCH_FEAT_SM101_ALL)
#define HAS_TCGEN05 1
#else
#define HAS_TCGEN05 0
#endif

// ---------------- scratch ----------------------------------------------------
__device__ float g_a1[BATCH * 128];
__device__ float g_a2[BATCH * 256];
__device__ float g_a3[BATCH * 128];
__device__ float g_psum[NRB * 256];
__device__ float g_psq [NRB * 256];
__device__ float g_scale[256];
__device__ float g_shift[256];
// Preformatted W tiles (tf32 hi/lo split, SW128-swizzled smem image).
// Each tile = 8192 floats (hi 16KB + lo 16KB). L1: 2 tiles @0, L2: 8 @16384,
// L3: 8 @81920. Total 147456 floats (576KB).
__device__ float g_wtiles[147456];

// ---------------- ptx helpers -------------------------------------------------
__device__ __forceinline__ uint32_t smem_u32(const void* p) {
    uint32_t a;
    asm("{ .reg .u64 t; cvta.to.shared.u64 t, %1; cvt.u32.u64 %0, t; }" : "=r"(a) : "l"(p));
    return a;
}

#if HAS_TCGEN05
__device__ __forceinline__ uint32_t elect1() {
    uint32_t p;
    asm volatile("{\n\t.reg .pred p;\n\telect.sync _|p, 0xFFFFFFFF;\n\tselp.b32 %0, 1, 0, p;\n\t}" : "=r"(p));
    return p;
}
#define TCGEN05_ALLOC(smem_addr, nCols) \
    asm volatile("tcgen05.alloc.cta_group::1.sync.aligned.shared::cta.b32 [%0], %1;" \
                 :: "r"((uint32_t)(smem_addr)), "r"((uint32_t)(nCols)) : "memory")
#define TCGEN05_DEALLOC(tmem_addr, nCols) \
    asm volatile("tcgen05.dealloc.cta_group::1.sync.aligned.b32 %0, %1;" \
                 :: "r"(tmem_addr), "r"((uint32_t)(nCols)))
#define TCGEN05_RELINQ() \
    asm volatile("tcgen05.relinquish_alloc_permit.cta_group::1.sync.aligned;")
#define TCGEN05_COMMIT(mbar_smem_addr) \
    asm volatile("tcgen05.commit.cta_group::1.mbarrier::arrive::one.shared::cluster.b64 [%0];" \
                 :: "r"((uint32_t)(mbar_smem_addr)) : "memory")
#define TCGEN05_FENCE_AFTER() \
    asm volatile("tcgen05.fence::after_thread_sync;" ::: "memory")
#define TCGEN05_WAIT_LD() \
    asm volatile("tcgen05.wait::ld.sync.aligned;" ::: "memory")
#define MBARRIER_INIT(mbar_smem_addr, count) \
    asm volatile("mbarrier.init.shared.b64 [%0], %1;" \
                 :: "r"((uint32_t)(mbar_smem_addr)), "r"((uint32_t)(count)) : "memory")
#define MBARRIER_WAIT_PARITY(mbar_smem_addr, phase_parity) do { \
    uint32_t _mbar = (uint32_t)(mbar_smem_addr); \
    uint32_t _parity = (uint32_t)(phase_parity); \
    uint32_t _done; \
    asm volatile("{\n\t.reg .pred p;\n\t" \
        "mbarrier.try_wait.parity.acquire.cta.shared::cta.b64 p, [%1], %2;\n\t" \
        "selp.b32 %0, 1, 0, p;\n\t}" \
        : "=r"(_done) : "r"(_mbar), "r"(_parity) : "memory"); \
    if (!_done) { \
        asm volatile("{\n\t.reg .pred P1;\n\t" \
            "WAIT_LOOP_%=:\n\t" \
            "mbarrier.try_wait.parity.acquire.cta.shared::cta.b64 P1, [%0], %1, 0x989680;\n\t" \
            "@P1 bra.uni WAIT_DONE_%=;\n\t" \
            "bra.uni WAIT_LOOP_%=;\n\t" \
            "WAIT_DONE_%=:\n\t}" \
            :: "r"(_mbar), "r"(_parity) : "memory"); \
    } \
} while (0)
#define TCGEN05_LD_32X32B_X32(r, tmem_addr) \
    asm volatile("tcgen05.ld.sync.aligned.32x32b.x32.b32 " \
        "{%0, %1, %2, %3, %4, %5, %6, %7, " \
        " %8, %9, %10, %11, %12, %13, %14, %15, " \
        " %16, %17, %18, %19, %20, %21, %22, %23, " \
        " %24, %25, %26, %27, %28, %29, %30, %31}, [%32];" \
        : "=r"((r)[0]),  "=r"((r)[1]),  "=r"((r)[2]),  "=r"((r)[3]), \
          "=r"((r)[4]),  "=r"((r)[5]),  "=r"((r)[6]),  "=r"((r)[7]), \
          "=r"((r)[8]),  "=r"((r)[9]),  "=r"((r)[10]), "=r"((r)[11]), \
          "=r"((r)[12]), "=r"((r)[13]), "=r"((r)[14]), "=r"((r)[15]), \
          "=r"((r)[16]), "=r"((r)[17]), "=r"((r)[18]), "=r"((r)[19]), \
          "=r"((r)[20]), "=r"((r)[21]), "=r"((r)[22]), "=r"((r)[23]), \
          "=r"((r)[24]), "=r"((r)[25]), "=r"((r)[26]), "=r"((r)[27]), \
          "=r"((r)[28]), "=r"((r)[29]), "=r"((r)[30]), "=r"((r)[31]) \
        : "r"(tmem_addr))

__device__ __forceinline__ uint64_t sdesc(uint32_t addr) {
    // SW128, version=1 (Blackwell), SBO=64, LBO=1, K-major
    return ((uint64_t)2 << 61) | ((uint64_t)1 << 46) | ((uint64_t)64 << 32) |
           ((uint64_t)1 << 16) | ((uint64_t)(addr >> 4) & 0x3FFF);
}
__device__ __forceinline__ void mma_tf32_ss(uint32_t d, uint64_t ad, uint64_t bd,
                                            uint32_t idesc, uint32_t en) {
    asm volatile("{\n\t.reg .pred p;\n\tsetp.ne.u32 p, %4, 0;\n\t"
        "tcgen05.mma.cta_group::1.kind::tf32 [%0], %1, %2, %3, {%5, %5, %5, %5}, p;\n\t}"
        :: "r"(d), "l"(ad), "l"(bd), "r"(idesc), "r"(en), "r"(0u) : "memory");
}
#endif // HAS_TCGEN05

#define SW128(o) ((o) ^ (((o) >> 3) & 0x70))

// ---------------------------------------------------------------------------
// prep_w: split W into tf32 hi/lo and lay out each (colblock, chunk) tile in
// the exact SW128 smem image. Lanes map to consecutive kk (coalesced 128B
// global stores); W reads are strided but tiny + L2-hot.
// grid = (NCH, CB), 256 threads.
// ---------------------------------------------------------------------------
__global__ void prep_w(const float* __restrict__ W, float* __restrict__ dst,
                       int Kdim, int N)
{
    const int ch = blockIdx.x, cb = blockIdx.y;
    const int NCH = gridDim.x;
    char* tile = (char*)(dst + (size_t)(cb * NCH + ch) * 8192);
    const int tid = threadIdx.x;
#pragma unroll
    for (int e = 0; e < 16; e++) {
        int idx = tid + e * 256;
        int n = idx >> 5, kk = idx & 31;
        int k = ch * 32 + kk;
        float v = (k < Kdim) ? W[(size_t)k * N + cb * 128 + n] : 0.f;
        uint32_t hb; asm("cvt.rna.tf32.f32 %0, %1;" : "=r"(hb) : "f"(v));
        float lo = v - __uint_as_float(hb);
        uint32_t off = SW128((uint32_t)(n * 128 + kk * 4));
        *(uint32_t*)(tile + off)         = hb;
        *(float*)   (tile + 16384 + off) = lo;
    }
}

// ---------------------------------------------------------------------------
// GEMM: C[B,N] = act(A[B,K]) @ W[K,N] + bias. tcgen05 path: 3xTF32 split,
// two-stage double buffer, B tiles copied preformatted from g_wtiles
// (conflict-free LDG.128/STS.128), A tiles vectorized when KDIM%4==0.
// ---------------------------------------------------------------------------
#define GEMM_SMEM (140 * 1024)

template<int KDIM, bool ACT>
__global__ __launch_bounds__(256, 1)
void gemm_tc(const float* __restrict__ A, const float* __restrict__ W,
             const float* __restrict__ wt, const float* __restrict__ bias,
             float* __restrict__ C, int N)
{
#if HAS_TCGEN05
    constexpr int NCH = (KDIM + 31) / 32;
    extern __shared__ char dsm[];
    const uint32_t sb0 = smem_u32(dsm);
    const uint32_t pad = ((sb0 + 1023) & ~1023u) - sb0;
    char* bp = dsm + pad;
    const uint32_t sbu = sb0 + pad;

    float* stage = (float*)bp;                // epilogue staging (reuse stage0)
    float* sSc   = (float*)(bp + 131072);
    float* sSh   = (float*)(bp + 132096);
    float* sB    = (float*)(bp + 133120);
    float* redS  = (float*)(bp + 133632);
    float* redQ  = (float*)(bp + 134656);

    __shared__ uint64_t s_mbar[2];
    __shared__ uint32_t s_tptr;
    const uint32_t mbA[2] = { smem_u32(&s_mbar[0]), smem_u32(&s_mbar[1]) };

    const int tid  = threadIdx.x;
    const int wid  = tid >> 5;
    const int lane = tid & 31;
    const int row0 = blockIdx.x * 128;
    const int col0 = blockIdx.y * 128;

    if (ACT) {
        for (int i = tid; i < KDIM; i += 256) { sSc[i] = g_scale[i]; sSh[i] = g_shift[i]; }
    }
    for (int i = tid; i < 128; i += 256) sB[i] = bias[col0 + i];
    if (tid == 0) { MBARRIER_INIT(mbA[0], 1); MBARRIER_INIT(mbA[1], 1); }
    if (wid == 0) TCGEN05_ALLOC(smem_u32(&s_tptr), 128);
    __syncthreads();
    const uint32_t tmem = s_tptr;

    const uint32_t IDESC = (1u << 4) | (2u << 7) | (2u << 10) | (16u << 17) | (8u << 24);

    for (int ch = 0; ch < NCH; ch++) {
        const int st  = ch & 1;
        const int use = ch >> 1;
        const uint32_t mb = mbA[st];
        if (use >= 1) { MBARRIER_WAIT_PARITY(mb, (use - 1) & 1); }

        char* pAh = bp + st * 65536;
        char* pAl = pAh + 16384;
        char* pBh = pAh + 32768;          // Bh||Bl contiguous 32KB
        const int k0 = ch * 32;

        // ---- B copy: preformatted tile, straight 32KB memcpy ----
        {
            const float4* src = (const float4*)(wt + (size_t)(blockIdx.y * NCH + ch) * 8192);
            float4* dst = (float4*)pBh;
#pragma unroll
            for (int i = 0; i < 8; i++) dst[tid + i * 256] = src[tid + i * 256];
        }

        // ---- A fill ----
        if (KDIM % 4 == 0) {
#pragma unroll
            for (int e = 0; e < 4; e++) {
                int f = tid + e * 256;            // float4 index 0..1023
                int m = f >> 3, kq = f & 7;
                float4 v4 = *(const float4*)(A + (size_t)(row0 + m) * KDIM + k0 + kq * 4);
                float vv[4] = {v4.x, v4.y, v4.z, v4.w};
                uint32_t hi[4]; float lo[4];
#pragma unroll
                for (int t = 0; t < 4; t++) {
                    float v = vv[t];
                    if (ACT) {
                        int k = k0 + kq * 4 + t;
                        v = fmaf(v, sSc[k], sSh[k]);
                        v = v > 0.f ? v : 0.2f * v;
                    }
                    asm("cvt.rna.tf32.f32 %0, %1;" : "=r"(hi[t]) : "f"(v));
                    lo[t] = v - __uint_as_float(hi[t]);
                }
                uint32_t off = SW128((uint32_t)(m * 128 + kq * 16));
                *(uint4*)(pAh + off)  = make_uint4(hi[0], hi[1], hi[2], hi[3]);
                *(float4*)(pAl + off) = make_float4(lo[0], lo[1], lo[2], lo[3]);
            }
        } else {
#pragma unroll
            for (int i = 0; i < 16; i++) {
                int idx = tid + i * 256;
                int m = idx >> 5, kk = idx & 31, k = k0 + kk;
                float v = 0.f;
                if (k < KDIM) {
                    v = A[(size_t)(row0 + m) * KDIM + k];
                    if (ACT) {
                        v = fmaf(v, sSc[k], sSh[k]);
                        v = v > 0.f ? v : 0.2f * v;
                    }
                }
                uint32_t hb; asm("cvt.rna.tf32.f32 %0, %1;" : "=r"(hb) : "f"(v));
                float lo = v - __uint_as_float(hb);
                uint32_t off = SW128((uint32_t)(m * 128 + kk * 4));
                *(uint32_t*)(pAh + off) = hb;
                *(float*)   (pAl + off) = lo;
            }
        }
        asm volatile("fence.proxy.async.shared::cta;" ::: "memory");
        __syncthreads();

        if (wid == 0 && elect1()) {
            const uint32_t sAh = sbu + st * 65536;
            uint64_t adh = sdesc(sAh),         adl = sdesc(sAh + 16384);
            uint64_t bdh = sdesc(sAh + 32768), bdl = sdesc(sAh + 49152);
#pragma unroll
            for (int ks = 0; ks < 4; ks++) {
                uint32_t en0 = (ch == 0 && ks == 0) ? 0u : 1u;
                mma_tf32_ss(tmem, adh + ks * 2, bdh + ks * 2, IDESC, en0);
                mma_tf32_ss(tmem, adh + ks * 2, bdl + ks * 2, IDESC, 1u);
                mma_tf32_ss(tmem, adl + ks * 2, bdh + ks * 2, IDESC, 1u);
            }
            TCGEN05_COMMIT(mb);
        }
    }
    MBARRIER_WAIT_PARITY(mbA[(NCH - 1) & 1], ((NCH - 1) >> 1) & 1);
    TCGEN05_FENCE_AFTER();
    __syncthreads();

    // ---- epilogue ----
    const int rw = wid & 3, cg = wid >> 2;
#pragma unroll 1
    for (int h = 0; h < 2; h++) {
        uint32_t regs[32];
        TCGEN05_LD_32X32B_X32(regs, tmem + h * 64 + cg * 32);
        TCGEN05_WAIT_LD();
        const int row = rw * 32 + lane;
#pragma unroll
        for (int j = 0; j < 32; j++) {
            float v = __uint_as_float(regs[j]) + sB[h * 64 + cg * 32 + j];
            stage[row * 67 + cg * 32 + j] = v;
        }
        __syncthreads();
        {
            const int col = tid & 63, rg4 = tid >> 6;
#pragma unroll 4
            for (int it = 0; it < 32; it++) {
                int r = it * 4 + rg4;
                C[(size_t)(row0 + r) * N + col0 + h * 64 + col] = stage[r * 67 + col];
            }
        }
        {
            const int col = tid & 63, rg = tid >> 6;
            float s = 0.f, q = 0.f;
#pragma unroll 8
            for (int r = rg * 32; r < rg * 32 + 32; r++) {
                float v = stage[r * 67 + col];
                s += v; q = fmaf(v, v, q);
            }
            redS[rg * 64 + col] = s;
            redQ[rg * 64 + col] = q;
        }
        __syncthreads();
        if (tid < 64) {
            float s = redS[tid] + redS[64 + tid] + redS[128 + tid] + redS[192 + tid];
            float q = redQ[tid] + redQ[64 + tid] + redQ[128 + tid] + redQ[192 + tid];
            g_psum[(size_t)blockIdx.x * N + col0 + h * 64 + tid] = s;
            g_psq [(size_t)blockIdx.x * N + col0 + h * 64 + tid] = q;
        }
        __syncthreads();
    }

    if (wid == 0) { TCGEN05_RELINQ(); TCGEN05_DEALLOC(tmem, 128); }

#else
    // ======================= FFMA fallback (plain sm_103 pass) ============
    extern __shared__ char dsm[];
    float (*As)[128] = (float(*)[128])dsm;
    float (*Ws)[128] = (float(*)[128])(dsm + 8192);
    float* sSc = (float*)(dsm + 16384);
    float* sSh = (float*)(dsm + 17408);

    const int tid  = threadIdx.x;
    const int row0 = blockIdx.x * 128;
    const int col0 = blockIdx.y * 128;

    if (ACT) {
        for (int i = tid; i < KDIM; i += 256) { sSc[i] = g_scale[i]; sSh[i] = g_shift[i]; }
        __syncthreads();
    }
    const int ty = tid >> 4;
    const int tx = tid & 15;

    float acc[8][8];
#pragma unroll
    for (int i = 0; i < 8; i++)
#pragma unroll
        for (int j = 0; j < 8; j++) acc[i][j] = 0.f;

    for (int k0 = 0; k0 < KDIM; k0 += 16) {
#pragma unroll
        for (int l = 0; l < 8; l++) {
            int idx = tid + l * 256;
            int m = idx >> 4, kk = idx & 15;
            int k = k0 + kk;
            float v = 0.f;
            if ((KDIM % 16 == 0) || k < KDIM) {
                v = A[(size_t)(row0 + m) * KDIM + k];
                if (ACT) {
                    v = fmaf(v, sSc[k], sSh[k]);
                    v = v > 0.f ? v : 0.2f * v;
                }
            }
            As[kk][m] = v;
        }
#pragma unroll
        for (int l = 0; l < 8; l++) {
            int idx = tid + l * 256;
            int kk = idx >> 7, n = idx & 127;
            int k = k0 + kk;
            Ws[kk][n] = ((KDIM % 16 == 0) || k < KDIM) ? W[(size_t)k * N + col0 + n] : 0.f;
        }
        __syncthreads();
#pragma unroll
        for (int kk = 0; kk < 16; kk++) {
            float4 a0 = *(const float4*)&As[kk][ty * 8];
            float4 a1 = *(const float4*)&As[kk][ty * 8 + 4];
            float4 w0 = *(const float4*)&Ws[kk][tx * 8];
            float4 w1 = *(const float4*)&Ws[kk][tx * 8 + 4];
            float a[8] = {a0.x, a0.y, a0.z, a0.w, a1.x, a1.y, a1.z, a1.w};
            float w[8] = {w0.x, w0.y, w0.z, w0.w, w1.x, w1.y, w1.z, w1.w};
#pragma unroll
            for (int i = 0; i < 8; i++)
#pragma unroll
                for (int j = 0; j < 8; j++)
                    acc[i][j] = fmaf(a[i], w[j], acc[i][j]);
        }
        __syncthreads();
    }

    float bj[8];
#pragma unroll
    for (int j = 0; j < 8; j++) bj[j] = bias[col0 + tx * 8 + j];
    float cs[8], cq[8];
#pragma unroll
    for (int j = 0; j < 8; j++) { cs[j] = 0.f; cq[j] = 0.f; }
#pragma unroll
    for (int i = 0; i < 8; i++) {
        float v[8];
#pragma unroll
        for (int j = 0; j < 8; j++) {
            v[j] = acc[i][j] + bj[j];
            cs[j] += v[j];
            cq[j] = fmaf(v[j], v[j], cq[j]);
        }
        float* cptr = &C[(size_t)(row0 + ty * 8 + i) * N + col0 + tx * 8];
        *(float4*)cptr       = make_float4(v[0], v[1], v[2], v[3]);
        *(float4*)(cptr + 4) = make_float4(v[4], v[5], v[6], v[7]);
    }
    float* red = &As[0][0];
    __syncthreads();
#pragma unroll
    for (int j = 0; j < 8; j++) red[ty * 128 + tx * 8 + j] = cs[j];
    __syncthreads();
    if (tid < 128) {
        float s = 0.f;
#pragma unroll
        for (int r = 0; r < 16; r++) s += red[r * 128 + tid];
        g_psum[(size_t)blockIdx.x * N + col0 + tid] = s;
    }
    __syncthreads();
#pragma unroll
    for (int j = 0; j < 8; j++) red[ty * 128 + tx * 8 + j] = cq[j];
    __syncthreads();
    if (tid < 128) {
        float s = 0.f;
#pragma unroll
        for (int r = 0; r < 16; r++) s += red[r * 128 + tid];
        g_psq[(size_t)blockIdx.x * N + col0 + tid] = s;
    }
#endif
}

// ---------------------------------------------------------------------------
__global__ void stats_kernel(const float* __restrict__ gamma,
                             const float* __restrict__ beta, int N)
{
    __shared__ float ss[128], qq[128];
    const int c = blockIdx.x;
    const int t = threadIdx.x;
    float s = 0.f, q = 0.f;
    for (int r = t; r < NRB; r += 128) {
        s += g_psum[(size_t)r * N + c];
        q += g_psq [(size_t)r * N + c];
    }
    ss[t] = s; qq[t] = q;
    __syncthreads();
    for (int off = 64; off > 0; off >>= 1) {
        if (t < off) { ss[t] += ss[t + off]; qq[t] += qq[t + off]; }
        __syncthreads();
    }
    if (t == 0) {
        float mean = ss[0] * (1.0f / (float)BATCH);
        float var  = qq[0] * (1.0f / (float)BATCH) - mean * mean;
        float inv  = rsqrtf(var + 1e-5f);
        float scl  = gamma[c] * inv;
        g_scale[c] = scl;
        g_shift[c] = beta[c] - mean * scl;
    }
}

// ---------------------------------------------------------------------------
__global__ __launch_bounds__(128)
void final_kernel(const float* __restrict__ W4, const float* __restrict__ b4,
                  const float* __restrict__ U, float* __restrict__ out)
{
    __shared__ float w4s[128 * 25];
    __shared__ float b4s[25];
    __shared__ float sc[128], sh[128];
    __shared__ __align__(16) float us[128 * 25];

    const int tid  = threadIdx.x;
    const int row0 = blockIdx.x * 128;
    const int row  = row0 + tid;

    for (int i = tid; i < 128 * 25; i += 128) w4s[i] = W4[i];
    if (tid < 25) b4s[tid] = b4[tid];
    sc[tid] = g_scale[tid];
    sh[tid] = g_shift[tid];
    __syncthreads();

    float lgt[25];
#pragma unroll
    for (int j = 0; j < 25; j++) lgt[j] = b4s[j];

    const float* arow = g_a3 + (size_t)row * 128;
    for (int k = 0; k < 128; k += 4) {
        float4 a4 = *(const float4*)(arow + k);
        float hv[4] = {a4.x, a4.y, a4.z, a4.w};
#pragma unroll
        for (int t = 0; t < 4; t++) {
            float h = fmaf(hv[t], sc[k + t], sh[k + t]);
            h = h > 0.f ? h : 0.2f * h;
#pragma unroll
            for (int j = 0; j < 25; j++)
                lgt[j] = fmaf(h, w4s[(k + t) * 25 + j], lgt[j]);
        }
    }

    unsigned mask = 0x1FFFFFFu;
#pragma unroll 1
    for (int s = 0; s < 15; s++) {
        __syncthreads();
        const float4* ub4 = (const float4*)(U + ((size_t)s * BATCH + row0) * 25);
        float4* us4 = (float4*)us;
        for (int i = tid; i < 800; i += 128) us4[i] = ub4[i];
        __syncthreads();

        float best = -CUDART_INF_F;
        int bi = __ffs(mask) - 1;
#pragma unroll
        for (int j = 0; j < 25; j++) {
            if (mask & (1u << j)) {
                float uu = us[tid * 25 + j];
                float nz = -__logf(-__logf(uu));
                float v  = lgt[j] + nz;
                if (v > best) { best = v; bi = j; }
            }
        }
        mask &= ~(1u << bi);
        out[(size_t)row * 15 + s] = (float)bi / 24.0f;
    }
}

// ---------------------------------------------------------------------------
extern "C" void kernel_launch(void* const* d_in, const int* in_sizes, int n_in,
                              void* d_out, int out_size)
{
    const float* z   = (const float*)d_in[0];
    const float* u   = (const float*)d_in[1];
    const float* W1  = (const float*)d_in[2];
    const float* b1  = (const float*)d_in[3];
    const float* g1  = (const float*)d_in[4];
    const float* be1 = (const float*)d_in[5];
    const float* W2  = (const float*)d_in[6];
    const float* b2  = (const float*)d_in[7];
    const float* g2  = (const float*)d_in[8];
    const float* be2 = (const float*)d_in[9];
    const float* W3  = (const float*)d_in[10];
    const float* b3  = (const float*)d_in[11];
    const float* g3  = (const float*)d_in[12];
    const float* be3 = (const float*)d_in[13];
    const float* W4  = (const float*)d_in[14];
    const float* b4  = (const float*)d_in[15];
    float* out = (float*)d_out;

    float *a1, *a2, *a3, *wt;
    cudaGetSymbolAddress((void**)&a1, g_a1);
    cudaGetSymbolAddress((void**)&a2, g_a2);
    cudaGetSymbolAddress((void**)&a3, g_a3);
    cudaGetSymbolAddress((void**)&wt, g_wtiles);
    float* wt1 = wt;            // L1: 2 tiles
    float* wt2 = wt + 16384;    // L2: 8 tiles (2 colblocks x 4 chunks)
    float* wt3 = wt + 81920;    // L3: 8 tiles (1 colblock x 8 chunks)

    cudaFuncSetAttribute(gemm_tc<50,  false>, cudaFuncAttributeMaxDynamicSharedMemorySize, GEMM_SMEM);
    cudaFuncSetAttribute(gemm_tc<128, true >, cudaFuncAttributeMaxDynamicSharedMemorySize, GEMM_SMEM);
    cudaFuncSetAttribute(gemm_tc<256, true >, cudaFuncAttributeMaxDynamicSharedMemorySize, GEMM_SMEM);

    // prep kernels first (also shifts ncu -s 5 capture onto gemm2)
    prep_w<<<dim3(2, 1), 256>>>(W1, wt1, 50, 128);
    prep_w<<<dim3(4, 2), 256>>>(W2, wt2, 128, 256);
    prep_w<<<dim3(8, 1), 256>>>(W3, wt3, 256, 128);

    gemm_tc<50,  false><<<dim3(NRB, 1), 256, GEMM_SMEM>>>(z,  W1, wt1, b1, a1, 128);
    stats_kernel<<<128, 128>>>(g1, be1, 128);
    gemm_tc<128, true ><<<dim3(NRB, 2), 256, GEMM_SMEM>>>(a1, W2, wt2, b2, a2, 256);
    stats_kernel<<<256, 128>>>(g2, be2, 256);
    gemm_tc<256, true ><<<dim3(NRB, 1), 256, GEMM_SMEM>>>(a2, W3, wt3, b3, a3, 128);
    stats_kernel<<<128, 128>>>(g3, be3, 128);
    final_kernel<<<NRB, 128>>>(W4, b4, u, out);
}

// round 6
// speedup vs baseline: 1.2608x; 1.1123x over previous
#include <cuda_runtime.h>
#include <cstdint>
#include <math_constants.h>

#define BATCH 131072
#define RPB   256              /* rows per CTA */
#define NPB   (BATCH / RPB)    /* 512 partial blocks */

#if defined(__CUDA_ARCH_FEAT_SM103_ALL) || defined(__CUDA_ARCH_FEAT_SM100_ALL) || defined(__CUDA_ARCH_FEAT_SM101_ALL)
#define HAS_TCGEN05 1
#else
#define HAS_TCGEN05 0
#endif

// ---------------- scratch ----------------------------------------------------
__device__ float g_a1[BATCH * 128];
__device__ float g_a2[BATCH * 256];
__device__ float g_a3[BATCH * 128];
__device__ float g_psum[256 * NPB];   // column-major: [col][rowblock]
__device__ float g_psq [256 * NPB];
__device__ float g_scale[256];
__device__ float g_shift[256];
// Preformatted W tiles (tf32 hi/lo split, SW128 smem image), 8192 floats each.
__device__ float g_wtiles[147456];

// ---------------- ptx helpers -------------------------------------------------
__device__ __forceinline__ uint32_t smem_u32(const void* p) {
    uint32_t a;
    asm("{ .reg .u64 t; cvta.to.shared.u64 t, %1; cvt.u32.u64 %0, t; }" : "=r"(a) : "l"(p));
    return a;
}

#if HAS_TCGEN05
__device__ __forceinline__ uint32_t elect1() {
    uint32_t p;
    asm volatile("{\n\t.reg .pred p;\n\telect.sync _|p, 0xFFFFFFFF;\n\tselp.b32 %0, 1, 0, p;\n\t}" : "=r"(p));
    return p;
}
#define TCGEN05_ALLOC(smem_addr, nCols) \
    asm volatile("tcgen05.alloc.cta_group::1.sync.aligned.shared::cta.b32 [%0], %1;" \
                 :: "r"((uint32_t)(smem_addr)), "r"((uint32_t)(nCols)) : "memory")
#define TCGEN05_DEALLOC(tmem_addr, nCols) \
    asm volatile("tcgen05.dealloc.cta_group::1.sync.aligned.b32 %0, %1;" \
                 :: "r"(tmem_addr), "r"((uint32_t)(nCols)))
#define TCGEN05_RELINQ() \
    asm volatile("tcgen05.relinquish_alloc_permit.cta_group::1.sync.aligned;")
#define TCGEN05_COMMIT(mbar_smem_addr) \
    asm volatile("tcgen05.commit.cta_group::1.mbarrier::arrive::one.shared::cluster.b64 [%0];" \
                 :: "r"((uint32_t)(mbar_smem_addr)) : "memory")
#define TCGEN05_FENCE_AFTER() \
    asm volatile("tcgen05.fence::after_thread_sync;" ::: "memory")
#define TCGEN05_WAIT_LD() \
    asm volatile("tcgen05.wait::ld.sync.aligned;" ::: "memory")
#define MBARRIER_INIT(mbar_smem_addr, count) \
    asm volatile("mbarrier.init.shared.b64 [%0], %1;" \
                 :: "r"((uint32_t)(mbar_smem_addr)), "r"((uint32_t)(count)) : "memory")
#define MBARRIER_WAIT_PARITY(mbar_smem_addr, phase_parity) do { \
    uint32_t _mbar = (uint32_t)(mbar_smem_addr); \
    uint32_t _parity = (uint32_t)(phase_parity); \
    uint32_t _done; \
    asm volatile("{\n\t.reg .pred p;\n\t" \
        "mbarrier.try_wait.parity.acquire.cta.shared::cta.b64 p, [%1], %2;\n\t" \
        "selp.b32 %0, 1, 0, p;\n\t}" \
        : "=r"(_done) : "r"(_mbar), "r"(_parity) : "memory"); \
    if (!_done) { \
        asm volatile("{\n\t.reg .pred P1;\n\t" \
            "WAIT_LOOP_%=:\n\t" \
            "mbarrier.try_wait.parity.acquire.cta.shared::cta.b64 P1, [%0], %1, 0x989680;\n\t" \
            "@P1 bra.uni WAIT_DONE_%=;\n\t" \
            "bra.uni WAIT_LOOP_%=;\n\t" \
            "WAIT_DONE_%=:\n\t}" \
            :: "r"(_mbar), "r"(_parity) : "memory"); \
    } \
} while (0)
#define TCGEN05_LD_32X32B_X32(r, tmem_addr) \
    asm volatile("tcgen05.ld.sync.aligned.32x32b.x32.b32 " \
        "{%0, %1, %2, %3, %4, %5, %6, %7, " \
        " %8, %9, %10, %11, %12, %13, %14, %15, " \
        " %16, %17, %18, %19, %20, %21, %22, %23, " \
        " %24, %25, %26, %27, %28, %29, %30, %31}, [%32];" \
        : "=r"((r)[0]),  "=r"((r)[1]),  "=r"((r)[2]),  "=r"((r)[3]), \
          "=r"((r)[4]),  "=r"((r)[5]),  "=r"((r)[6]),  "=r"((r)[7]), \
          "=r"((r)[8]),  "=r"((r)[9]),  "=r"((r)[10]), "=r"((r)[11]), \
          "=r"((r)[12]), "=r"((r)[13]), "=r"((r)[14]), "=r"((r)[15]), \
          "=r"((r)[16]), "=r"((r)[17]), "=r"((r)[18]), "=r"((r)[19]), \
          "=r"((r)[20]), "=r"((r)[21]), "=r"((r)[22]), "=r"((r)[23]), \
          "=r"((r)[24]), "=r"((r)[25]), "=r"((r)[26]), "=r"((r)[27]), \
          "=r"((r)[28]), "=r"((r)[29]), "=r"((r)[30]), "=r"((r)[31]) \
        : "r"(tmem_addr))

__device__ __forceinline__ uint64_t sdesc(uint32_t addr) {
    return ((uint64_t)2 << 61) | ((uint64_t)1 << 46) | ((uint64_t)64 << 32) |
           ((uint64_t)1 << 16) | ((uint64_t)(addr >> 4) & 0x3FFF);
}
__device__ __forceinline__ void mma_tf32_ss(uint32_t d, uint64_t ad, uint64_t bd,
                                            uint32_t idesc, uint32_t en) {
    asm volatile("{\n\t.reg .pred p;\n\tsetp.ne.u32 p, %4, 0;\n\t"
        "tcgen05.mma.cta_group::1.kind::tf32 [%0], %1, %2, %3, {%5, %5, %5, %5}, p;\n\t}"
        :: "r"(d), "l"(ad), "l"(bd), "r"(idesc), "r"(en), "r"(0u) : "memory");
}
#endif // HAS_TCGEN05

#define SW128(o) ((o) ^ (((o) >> 3) & 0x70))

// ---------------------------------------------------------------------------
__global__ void prep_w(const float* __restrict__ W, float* __restrict__ dst,
                       int Kdim, int N)
{
    const int ch = blockIdx.x, cb = blockIdx.y;
    const int NCH = gridDim.x;
    char* tile = (char*)(dst + (size_t)(cb * NCH + ch) * 8192);
    const int tid = threadIdx.x;
#pragma unroll
    for (int e = 0; e < 16; e++) {
        int idx = tid + e * 256;
        int n = idx >> 5, kk = idx & 31;
        int k = ch * 32 + kk;
        float v = (k < Kdim) ? W[(size_t)k * N + cb * 128 + n] : 0.f;
        uint32_t hb; asm("cvt.rna.tf32.f32 %0, %1;" : "=r"(hb) : "f"(v));
        float lo = v - __uint_as_float(hb);
        uint32_t off = SW128((uint32_t)(n * 128 + kk * 4));
        *(uint32_t*)(tile + off)         = hb;
        *(float*)   (tile + 16384 + off) = lo;
    }
}

// ---------------------------------------------------------------------------
// GEMM, M=256 per CTA: two 128x128 D tiles (TMEM cols 0..255), shared B tile.
// Two-stage double buffer. smem stage (96KB): A0h/A0l/A1h/A1l/Bh/Bl @16KB ea.
// ---------------------------------------------------------------------------
#define STAGE_SZ 98304
#define EX_OFF   196608
#define GEMM_SMEM (204 * 1024)

template<int KDIM, bool ACT>
__global__ __launch_bounds__(256, 1)
void gemm_tc(const float* __restrict__ A, const float* __restrict__ W,
             const float* __restrict__ wt, const float* __restrict__ bias,
             float* __restrict__ C, int N)
{
#if HAS_TCGEN05
    constexpr int NCH = (KDIM + 31) / 32;
    extern __shared__ char dsm[];
    const uint32_t sb0 = smem_u32(dsm);
    const uint32_t pad = ((sb0 + 1023) & ~1023u) - sb0;
    char* bp = dsm + pad;
    const uint32_t sbu = sb0 + pad;

    float* stage = (float*)bp;                // epilogue staging (reuse stage0)
    float* sSc   = (float*)(bp + EX_OFF);
    float* sSh   = (float*)(bp + EX_OFF + 1024);
    float* sB    = (float*)(bp + EX_OFF + 2048);
    float* redS  = (float*)(bp + EX_OFF + 2560);
    float* redQ  = (float*)(bp + EX_OFF + 3584);

    __shared__ uint64_t s_mbar[2];
    __shared__ uint32_t s_tptr;
    const uint32_t mbA[2] = { smem_u32(&s_mbar[0]), smem_u32(&s_mbar[1]) };

    const int tid  = threadIdx.x;
    const int wid  = tid >> 5;
    const int lane = tid & 31;
    const int row0 = blockIdx.x * RPB;
    const int col0 = blockIdx.y * 128;

    if (ACT) {
        for (int i = tid; i < KDIM; i += 256) { sSc[i] = g_scale[i]; sSh[i] = g_shift[i]; }
    }
    for (int i = tid; i < 128; i += 256) sB[i] = bias[col0 + i];
    if (tid == 0) { MBARRIER_INIT(mbA[0], 1); MBARRIER_INIT(mbA[1], 1); }
    if (wid == 0) TCGEN05_ALLOC(smem_u32(&s_tptr), 512);
    __syncthreads();
    const uint32_t tmem = s_tptr;

    const uint32_t IDESC = (1u << 4) | (2u << 7) | (2u << 10) | (16u << 17) | (8u << 24);

    for (int ch = 0; ch < NCH; ch++) {
        const int st  = ch & 1;
        const int use = ch >> 1;
        const uint32_t mb = mbA[st];
        if (use >= 1) { MBARRIER_WAIT_PARITY(mb, (use - 1) & 1); }

        char* ps  = bp + st * STAGE_SZ;
        const int k0 = ch * 32;

        // ---- B copy: preformatted 32KB tile ----
        {
            const float4* src = (const float4*)(wt + (size_t)(blockIdx.y * NCH + ch) * 8192);
            float4* dst = (float4*)(ps + 65536);
#pragma unroll
            for (int i = 0; i < 8; i++) dst[tid + i * 256] = src[tid + i * 256];
        }

        // ---- A fill: two row tiles ----
#pragma unroll
        for (int t = 0; t < 2; t++) {
            char* pAh = ps + t * 32768;
            char* pAl = pAh + 16384;
            const int rbase = row0 + t * 128;
            if (KDIM % 4 == 0) {
#pragma unroll
                for (int e = 0; e < 4; e++) {
                    int f = tid + e * 256;
                    int m = f >> 3, kq = f & 7;
                    float4 v4 = *(const float4*)(A + (size_t)(rbase + m) * KDIM + k0 + kq * 4);
                    float vv[4] = {v4.x, v4.y, v4.z, v4.w};
                    uint32_t hi[4]; float lo[4];
#pragma unroll
                    for (int u = 0; u < 4; u++) {
                        float v = vv[u];
                        if (ACT) {
                            int k = k0 + kq * 4 + u;
                            v = fmaf(v, sSc[k], sSh[k]);
                            v = v > 0.f ? v : 0.2f * v;
                        }
                        asm("cvt.rna.tf32.f32 %0, %1;" : "=r"(hi[u]) : "f"(v));
                        lo[u] = v - __uint_as_float(hi[u]);
                    }
                    uint32_t off = SW128((uint32_t)(m * 128 + kq * 16));
                    *(uint4*)(pAh + off)  = make_uint4(hi[0], hi[1], hi[2], hi[3]);
                    *(float4*)(pAl + off) = make_float4(lo[0], lo[1], lo[2], lo[3]);
                }
            } else {
#pragma unroll
                for (int i = 0; i < 16; i++) {
                    int idx = tid + i * 256;
                    int m = idx >> 5, kk = idx & 31, k = k0 + kk;
                    float v = 0.f;
                    if (k < KDIM) {
                        v = A[(size_t)(rbase + m) * KDIM + k];
                        if (ACT) {
                            v = fmaf(v, sSc[k], sSh[k]);
                            v = v > 0.f ? v : 0.2f * v;
                        }
                    }
                    uint32_t hb; asm("cvt.rna.tf32.f32 %0, %1;" : "=r"(hb) : "f"(v));
                    float lo = v - __uint_as_float(hb);
                    uint32_t off = SW128((uint32_t)(m * 128 + kk * 4));
                    *(uint32_t*)(pAh + off) = hb;
                    *(float*)   (pAl + off) = lo;
                }
            }
        }
        asm volatile("fence.proxy.async.shared::cta;" ::: "memory");
        __syncthreads();

        if (wid == 0 && elect1()) {
            const uint32_t sbase = sbu + st * STAGE_SZ;
            uint64_t bdh = sdesc(sbase + 65536), bdl = sdesc(sbase + 81920);
#pragma unroll
            for (int t = 0; t < 2; t++) {
                uint64_t adh = sdesc(sbase + t * 32768);
                uint64_t adl = sdesc(sbase + t * 32768 + 16384);
                uint32_t dofs = tmem + t * 128;
#pragma unroll
                for (int ks = 0; ks < 4; ks++) {
                    uint32_t en0 = (ch == 0 && ks == 0) ? 0u : 1u;
                    mma_tf32_ss(dofs, adh + ks * 2, bdh + ks * 2, IDESC, en0);
                    mma_tf32_ss(dofs, adh + ks * 2, bdl + ks * 2, IDESC, 1u);
                    mma_tf32_ss(dofs, adl + ks * 2, bdh + ks * 2, IDESC, 1u);
                }
            }
            TCGEN05_COMMIT(mb);
        }
    }
    MBARRIER_WAIT_PARITY(mbA[(NCH - 1) & 1], ((NCH - 1) >> 1) & 1);
    TCGEN05_FENCE_AFTER();
    __syncthreads();

    // ---- epilogue: (h = col half) x (t = row tile) through smem staging ----
    const int rw = wid & 3, cg = wid >> 2;
#pragma unroll 1
    for (int h = 0; h < 2; h++) {
        const int colS = tid & 63, rg = tid >> 6;
        float sAcc = 0.f, qAcc = 0.f;
#pragma unroll 1
        for (int t = 0; t < 2; t++) {
            uint32_t regs[32];
            TCGEN05_LD_32X32B_X32(regs, tmem + t * 128 + h * 64 + cg * 32);
            TCGEN05_WAIT_LD();
            const int row = rw * 32 + lane;
#pragma unroll
            for (int j = 0; j < 32; j++) {
                float v = __uint_as_float(regs[j]) + sB[h * 64 + cg * 32 + j];
                stage[row * 67 + cg * 32 + j] = v;
            }
            __syncthreads();
            {   // coalesced store of this 128x64 slab
#pragma unroll 4
                for (int it = 0; it < 32; it++) {
                    int r = it * 4 + rg;
                    C[(size_t)(row0 + t * 128 + r) * N + col0 + h * 64 + colS] =
                        stage[r * 67 + colS];
                }
            }
            {   // column stats accumulate (4 row-groups x 64 cols)
#pragma unroll 8
                for (int r = rg * 32; r < rg * 32 + 32; r++) {
                    float v = stage[r * 67 + colS];
                    sAcc += v; qAcc = fmaf(v, v, qAcc);
                }
            }
            __syncthreads();
        }
        redS[rg * 64 + colS] = sAcc;
        redQ[rg * 64 + colS] = qAcc;
        __syncthreads();
        if (tid < 64) {
            float s = redS[tid] + redS[64 + tid] + redS[128 + tid] + redS[192 + tid];
            float q = redQ[tid] + redQ[64 + tid] + redQ[128 + tid] + redQ[192 + tid];
            int c = col0 + h * 64 + tid;
            g_psum[(size_t)c * NPB + blockIdx.x] = s;
            g_psq [(size_t)c * NPB + blockIdx.x] = q;
        }
        __syncthreads();
    }

    if (wid == 0) { TCGEN05_RELINQ(); TCGEN05_DEALLOC(tmem, 512); }

#else
    // ======================= FFMA fallback (plain sm_103 pass) ============
    extern __shared__ char dsm[];
    float (*As)[128] = (float(*)[128])dsm;
    float (*Ws)[128] = (float(*)[128])(dsm + 8192);
    float* sSc = (float*)(dsm + 16384);
    float* sSh = (float*)(dsm + 17408);

    const int tid  = threadIdx.x;
    const int col0 = blockIdx.y * 128;

    if (ACT) {
        for (int i = tid; i < KDIM; i += 256) { sSc[i] = g_scale[i]; sSh[i] = g_shift[i]; }
        __syncthreads();
    }
    const int ty = tid >> 4;
    const int tx = tid & 15;

    float cs[8], cq[8];
#pragma unroll
    for (int j = 0; j < 8; j++) { cs[j] = 0.f; cq[j] = 0.f; }
    float bj[8];
#pragma unroll
    for (int j = 0; j < 8; j++) bj[j] = bias[col0 + tx * 8 + j];

#pragma unroll 1
    for (int rt = 0; rt < 2; rt++) {
        const int row0 = blockIdx.x * RPB + rt * 128;
        float acc[8][8];
#pragma unroll
        for (int i = 0; i < 8; i++)
#pragma unroll
            for (int j = 0; j < 8; j++) acc[i][j] = 0.f;

        for (int k0 = 0; k0 < KDIM; k0 += 16) {
#pragma unroll
            for (int l = 0; l < 8; l++) {
                int idx = tid + l * 256;
                int m = idx >> 4, kk = idx & 15;
                int k = k0 + kk;
                float v = 0.f;
                if ((KDIM % 16 == 0) || k < KDIM) {
                    v = A[(size_t)(row0 + m) * KDIM + k];
                    if (ACT) {
                        v = fmaf(v, sSc[k], sSh[k]);
                        v = v > 0.f ? v : 0.2f * v;
                    }
                }
                As[kk][m] = v;
            }
#pragma unroll
            for (int l = 0; l < 8; l++) {
                int idx = tid + l * 256;
                int kk = idx >> 7, n = idx & 127;
                int k = k0 + kk;
                Ws[kk][n] = ((KDIM % 16 == 0) || k < KDIM) ? W[(size_t)k * N + col0 + n] : 0.f;
            }
            __syncthreads();
#pragma unroll
            for (int kk = 0; kk < 16; kk++) {
                float4 a0 = *(const float4*)&As[kk][ty * 8];
                float4 a1 = *(const float4*)&As[kk][ty * 8 + 4];
                float4 w0 = *(const float4*)&Ws[kk][tx * 8];
                float4 w1 = *(const float4*)&Ws[kk][tx * 8 + 4];
                float a[8] = {a0.x, a0.y, a0.z, a0.w, a1.x, a1.y, a1.z, a1.w};
                float w[8] = {w0.x, w0.y, w0.z, w0.w, w1.x, w1.y, w1.z, w1.w};
#pragma unroll
                for (int i = 0; i < 8; i++)
#pragma unroll
                    for (int j = 0; j < 8; j++)
                        acc[i][j] = fmaf(a[i], w[j], acc[i][j]);
            }
            __syncthreads();
        }
#pragma unroll
        for (int i = 0; i < 8; i++) {
            float v[8];
#pragma unroll
            for (int j = 0; j < 8; j++) {
                v[j] = acc[i][j] + bj[j];
                cs[j] += v[j];
                cq[j] = fmaf(v[j], v[j], cq[j]);
            }
            float* cptr = &C[(size_t)(row0 + ty * 8 + i) * N + col0 + tx * 8];
            *(float4*)cptr       = make_float4(v[0], v[1], v[2], v[3]);
            *(float4*)(cptr + 4) = make_float4(v[4], v[5], v[6], v[7]);
        }
        __syncthreads();
    }

    float* red = &As[0][0];
#pragma unroll
    for (int j = 0; j < 8; j++) red[ty * 128 + tx * 8 + j] = cs[j];
    __syncthreads();
    if (tid < 128) {
        float s = 0.f;
#pragma unroll
        for (int r = 0; r < 16; r++) s += red[r * 128 + tid];
        g_psum[(size_t)(col0 + tid) * NPB + blockIdx.x] = s;
    }
    __syncthreads();
#pragma unroll
    for (int j = 0; j < 8; j++) red[ty * 128 + tx * 8 + j] = cq[j];
    __syncthreads();
    if (tid < 128) {
        float s = 0.f;
#pragma unroll
        for (int r = 0; r < 16; r++) s += red[r * 128 + tid];
        g_psq[(size_t)(col0 + tid) * NPB + blockIdx.x] = s;
    }
#endif
}

// ---------------------------------------------------------------------------
// stats: column-major partials -> contiguous reads. One block per column.
// ---------------------------------------------------------------------------
__global__ void stats_kernel(const float* __restrict__ gamma,
                             const float* __restrict__ beta, int N)
{
    __shared__ float ss[128], qq[128];
    const int c = blockIdx.x;
    const int t = threadIdx.x;
    const float* bs = g_psum + (size_t)c * NPB;
    const float* bq = g_psq  + (size_t)c * NPB;
    float s = bs[t] + bs[t + 128] + bs[t + 256] + bs[t + 384];
    float q = bq[t] + bq[t + 128] + bq[t + 256] + bq[t + 384];
    ss[t] = s; qq[t] = q;
    __syncthreads();
    for (int off = 64; off > 0; off >>= 1) {
        if (t < off) { ss[t] += ss[t + off]; qq[t] += qq[t + off]; }
        __syncthreads();
    }
    if (t == 0) {
        float mean = ss[0] * (1.0f / (float)BATCH);
        float var  = qq[0] * (1.0f / (float)BATCH) - mean * mean;
        float inv  = rsqrtf(var + 1e-5f);
        float scl  = gamma[c] * inv;
        g_scale[c] = scl;
        g_shift[c] = beta[c] - mean * scl;
    }
}

// ---------------------------------------------------------------------------
__global__ __launch_bounds__(128)
void final_kernel(const float* __restrict__ W4, const float* __restrict__ b4,
                  const float* __restrict__ U, float* __restrict__ out)
{
    __shared__ float w4s[128 * 25];
    __shared__ float b4s[25];
    __shared__ float sc[128], sh[128];
    __shared__ __align__(16) float us[128 * 25];

    const int tid  = threadIdx.x;
    const int row0 = blockIdx.x * 128;
    const int row  = row0 + tid;

    for (int i = tid; i < 128 * 25; i += 128) w4s[i] = W4[i];
    if (tid < 25) b4s[tid] = b4[tid];
    sc[tid] = g_scale[tid];
    sh[tid] = g_shift[tid];
    __syncthreads();

    float lgt[25];
#pragma unroll
    for (int j = 0; j < 25; j++) lgt[j] = b4s[j];

    const float* arow = g_a3 + (size_t)row * 128;
    for (int k = 0; k < 128; k += 4) {
        float4 a4 = *(const float4*)(arow + k);
        float hv[4] = {a4.x, a4.y, a4.z, a4.w};
#pragma unroll
        for (int t = 0; t < 4; t++) {
            float h = fmaf(hv[t], sc[k + t], sh[k + t]);
            h = h > 0.f ? h : 0.2f * h;
#pragma unroll
            for (int j = 0; j < 25; j++)
                lgt[j] = fmaf(h, w4s[(k + t) * 25 + j], lgt[j]);
        }
    }

    unsigned mask = 0x1FFFFFFu;
#pragma unroll 1
    for (int s = 0; s < 15; s++) {
        __syncthreads();
        const float4* ub4 = (const float4*)(U + ((size_t)s * BATCH + row0) * 25);
        float4* us4 = (float4*)us;
        for (int i = tid; i < 800; i += 128) us4[i] = ub4[i];
        __syncthreads();

        float best = -CUDART_INF_F;
        int bi = __ffs(mask) - 1;
#pragma unroll
        for (int j = 0; j < 25; j++) {
            if (mask & (1u << j)) {
                float uu = us[tid * 25 + j];
                float nz = -__logf(-__logf(uu));
                float v  = lgt[j] + nz;
                if (v > best) { best = v; bi = j; }
            }
        }
        mask &= ~(1u << bi);
        out[(size_t)row * 15 + s] = (float)bi / 24.0f;
    }
}

// ---------------------------------------------------------------------------
extern "C" void kernel_launch(void* const* d_in, const int* in_sizes, int n_in,
                              void* d_out, int out_size)
{
    const float* z   = (const float*)d_in[0];
    const float* u   = (const float*)d_in[1];
    const float* W1  = (const float*)d_in[2];
    const float* b1  = (const float*)d_in[3];
    const float* g1  = (const float*)d_in[4];
    const float* be1 = (const float*)d_in[5];
    const float* W2  = (const float*)d_in[6];
    const float* b2  = (const float*)d_in[7];
    const float* g2  = (const float*)d_in[8];
    const float* be2 = (const float*)d_in[9];
    const float* W3  = (const float*)d_in[10];
    const float* b3  = (const float*)d_in[11];
    const float* g3  = (const float*)d_in[12];
    const float* be3 = (const float*)d_in[13];
    const float* W4  = (const float*)d_in[14];
    const float* b4  = (const float*)d_in[15];
    float* out = (float*)d_out;

    float *a1, *a2, *a3, *wt;
    cudaGetSymbolAddress((void**)&a1, g_a1);
    cudaGetSymbolAddress((void**)&a2, g_a2);
    cudaGetSymbolAddress((void**)&a3, g_a3);
    cudaGetSymbolAddress((void**)&wt, g_wtiles);
    float* wt1 = wt;            // L1: 2 tiles
    float* wt2 = wt + 16384;    // L2: 8 tiles
    float* wt3 = wt + 81920;    // L3: 8 tiles

    cudaFuncSetAttribute(gemm_tc<50,  false>, cudaFuncAttributeMaxDynamicSharedMemorySize, GEMM_SMEM);
    cudaFuncSetAttribute(gemm_tc<128, true >, cudaFuncAttributeMaxDynamicSharedMemorySize, GEMM_SMEM);
    cudaFuncSetAttribute(gemm_tc<256, true >, cudaFuncAttributeMaxDynamicSharedMemorySize, GEMM_SMEM);

    prep_w<<<dim3(2, 1), 256>>>(W1, wt1, 50, 128);
    prep_w<<<dim3(4, 2), 256>>>(W2, wt2, 128, 256);
    prep_w<<<dim3(8, 1), 256>>>(W3, wt3, 256, 128);

    gemm_tc<50,  false><<<dim3(NPB, 1), 256, GEMM_SMEM>>>(z,  W1, wt1, b1, a1, 128);
    stats_kernel<<<128, 128>>>(g1, be1, 128);
    gemm_tc<128, true ><<<dim3(NPB, 2), 256, GEMM_SMEM>>>(a1, W2, wt2, b2, a2, 256);
    stats_kernel<<<256, 128>>>(g2, be2, 256);
    gemm_tc<256, true ><<<dim3(NPB, 1), 256, GEMM_SMEM>>>(a2, W3, wt3, b3, a3, 128);
    stats_kernel<<<128, 128>>>(g3, be3, 128);
    final_kernel<<<1024, 128>>>(W4, b4, u, out);
}